// round 4
// baseline (speedup 1.0000x reference)
#include <cuda_runtime.h>
#include <cstdint>

#define BSZ 4
#define LM  256
#define LE  512
#define HD  512
#define VOC 32000

// Scratch (device globals; no allocation allowed in kernel_launch)
__device__ float g_G[HD * HD];            // W_m @ W_e^T * H^-0.5   (1 MB)
__device__ float g_T[BSZ * LM * HD];      // M @ G                  (2 MB)
__device__ float g_logits[BSZ * LM * LE]; // T @ E^T                (2 MB)
__device__ float g_lam[BSZ * LM];

// ---------------------------------------------------------------------------
// lambda = sigmoid(concat(D, Cq, Cc) @ W_lambda + b_lambda), one block per row
// ---------------------------------------------------------------------------
__global__ __launch_bounds__(256) void k_lambda(
    const float* __restrict__ D, const float* __restrict__ Cq,
    const float* __restrict__ Cc, const float* __restrict__ Wl,
    const float* __restrict__ bl)
{
    int r = blockIdx.x;
    int t = threadIdx.x;
    const float* d  = D  + (long)r * HD;
    const float* cq = Cq + (long)r * HD;
    const float* cc = Cc + (long)r * HD;
    float s = 0.f;
    for (int j = t; j < HD; j += 256)
        s += d[j] * Wl[j] + cq[j] * Wl[HD + j] + cc[j] * Wl[2 * HD + j];
    __shared__ float red[256];
    red[t] = s; __syncthreads();
    for (int o = 128; o > 0; o >>= 1) {
        if (t < o) red[t] += red[t + o];
        __syncthreads();
    }
    if (t == 0) {
        float x = red[0] + bl[0];
        g_lam[r] = 1.f / (1.f + __expf(-x));
    }
}

// ---------------------------------------------------------------------------
// tf32 tensor-core GEMM: 64x64 block tile, 128 threads (2x2 warps of 32x32),
// BK=32, cp.async double-buffered smem, mma.sync.m16n8k8.tf32.
// TB=true:  C[m,n] = alpha * sum_k A[m,k] * B[n,k]   (NT, both K-major)
// TB=false: C[m,n] = alpha * sum_k A[m,k] * B[k,n]   (NN)
// K fixed = 512. Batched via blockIdx.z.
// ---------------------------------------------------------------------------
__device__ __forceinline__ void cp16(void* dst, const void* src)
{
    uint32_t d = (uint32_t)__cvta_generic_to_shared(dst);
    asm volatile("cp.async.cg.shared.global [%0], [%1], 16;\n"
                 :: "r"(d), "l"(src));
}
__device__ __forceinline__ void cp_commit()
{
    asm volatile("cp.async.commit_group;\n" ::: "memory");
}
__device__ __forceinline__ void cp_wait0()
{
    asm volatile("cp.async.wait_group 0;\n" ::: "memory");
}
__device__ __forceinline__ void mma_tf32(float* d, const uint32_t* a,
                                         const uint32_t* b)
{
    asm volatile(
        "mma.sync.aligned.m16n8k8.row.col.f32.tf32.tf32.f32 "
        "{%0,%1,%2,%3}, {%4,%5,%6,%7}, {%8,%9}, {%0,%1,%2,%3};\n"
        : "+f"(d[0]), "+f"(d[1]), "+f"(d[2]), "+f"(d[3])
        : "r"(a[0]), "r"(a[1]), "r"(a[2]), "r"(a[3]),
          "r"(b[0]), "r"(b[1]));
}

#define PA 36   // smem pitch for K-major tiles (banks: 4*gid+tig, conflict-free)
#define PB 72   // smem pitch for NN B tile    (banks: 8*tig+gid, conflict-free)

template <bool TB>
__global__ __launch_bounds__(128) void k_gemm_tc(
    const float* __restrict__ A, const float* __restrict__ B,
    float* __restrict__ C, int lda, int ldb, int ldc,
    long strA, long strB, long strC, float alpha)
{
    __shared__ float As[2][64 * PA];
    __shared__ float Bs[2][2304];   // NT: 64*PA, NN: 32*PB (both 2304 floats)

    long bz = blockIdx.z;
    A += bz * strA; B += bz * strB; C += bz * strC;
    const int m0 = blockIdx.y * 64, n0 = blockIdx.x * 64;

    const int tid  = threadIdx.x;
    const int lane = tid & 31, w = tid >> 5;
    const int gid = lane >> 2, tig = lane & 3;
    const int wm = (w & 1) * 32, wn = (w >> 1) * 32;

    const int NK = HD / 32;  // 16 mainloop iters

    // tile loaders: 512 16B chunks per tile, 4 per thread
    auto loadA = [&](int buf, int kt) {
        int k0 = kt * 32;
#pragma unroll
        for (int i = 0; i < 4; i++) {
            int id = tid + i * 128;
            int row = id >> 3, cc = id & 7;
            cp16(&As[buf][row * PA + cc * 4],
                 A + (long)(m0 + row) * lda + k0 + cc * 4);
        }
    };
    auto loadB = [&](int buf, int kt) {
        int k0 = kt * 32;
        if (TB) {
#pragma unroll
            for (int i = 0; i < 4; i++) {
                int id = tid + i * 128;
                int row = id >> 3, cc = id & 7;
                cp16(&Bs[buf][row * PA + cc * 4],
                     B + (long)(n0 + row) * ldb + k0 + cc * 4);
            }
        } else {
#pragma unroll
            for (int i = 0; i < 4; i++) {
                int id = tid + i * 128;
                int row = id >> 4, cc = id & 15;
                cp16(&Bs[buf][row * PB + cc * 4],
                     B + (long)(k0 + row) * ldb + n0 + cc * 4);
            }
        }
    };

    float acc[2][4][4] = {};

    loadA(0, 0); loadB(0, 0); cp_commit();
    cp_wait0(); __syncthreads();

    int buf = 0;
    for (int kt = 0; kt < NK; kt++) {
        if (kt + 1 < NK) {
            loadA(buf ^ 1, kt + 1);
            loadB(buf ^ 1, kt + 1);
            cp_commit();
        }
#pragma unroll
        for (int ks = 0; ks < 4; ks++) {
            const int kk = ks * 8;
            uint32_t a[2][4];
#pragma unroll
            for (int mi = 0; mi < 2; mi++) {
                int rb = wm + mi * 16 + gid;
                a[mi][0] = __float_as_uint(As[buf][(rb)     * PA + kk + tig]);
                a[mi][1] = __float_as_uint(As[buf][(rb + 8) * PA + kk + tig]);
                a[mi][2] = __float_as_uint(As[buf][(rb)     * PA + kk + tig + 4]);
                a[mi][3] = __float_as_uint(As[buf][(rb + 8) * PA + kk + tig + 4]);
            }
            uint32_t b[4][2];
#pragma unroll
            for (int nj = 0; nj < 4; nj++) {
                int cb = wn + nj * 8 + gid;
                if (TB) {
                    b[nj][0] = __float_as_uint(Bs[buf][cb * PA + kk + tig]);
                    b[nj][1] = __float_as_uint(Bs[buf][cb * PA + kk + tig + 4]);
                } else {
                    b[nj][0] = __float_as_uint(Bs[buf][(kk + tig)     * PB + cb]);
                    b[nj][1] = __float_as_uint(Bs[buf][(kk + tig + 4) * PB + cb]);
                }
            }
#pragma unroll
            for (int mi = 0; mi < 2; mi++)
#pragma unroll
                for (int nj = 0; nj < 4; nj++)
                    mma_tf32(acc[mi][nj], a[mi], b[nj]);
        }
        if (kt + 1 < NK) {
            cp_wait0(); __syncthreads();
            buf ^= 1;
        }
    }

#pragma unroll
    for (int mi = 0; mi < 2; mi++)
#pragma unroll
        for (int nj = 0; nj < 4; nj++) {
            int r0 = m0 + wm + mi * 16 + gid;
            int c0 = n0 + wn + nj * 8 + 2 * tig;
            C[(long)r0 * ldc + c0]           = acc[mi][nj][0] * alpha;
            C[(long)r0 * ldc + c0 + 1]       = acc[mi][nj][1] * alpha;
            C[(long)(r0 + 8) * ldc + c0]     = acc[mi][nj][2] * alpha;
            C[(long)(r0 + 8) * ldc + c0 + 1] = acc[mi][nj][3] * alpha;
        }
}

// ---------------------------------------------------------------------------
// One block per (b,m) row: zero the 32000-float output row, dual softmax over
// the shared logits row (with the two bias vectors), combine with lambda,
// scatter-add at inputs[b,e].
// ---------------------------------------------------------------------------
__global__ __launch_bounds__(256) void k_softmax_scatter(
    const int* __restrict__ idx, const float* __restrict__ bq,
    const float* __restrict__ bc, float* __restrict__ out)
{
    int r = blockIdx.x;
    int b = r / LM;
    int t = threadIdx.x;

    float* orow = out + (long)r * VOC;
    float4 z = make_float4(0.f, 0.f, 0.f, 0.f);
    float4* orow4 = (float4*)orow;
    for (int i = t; i < VOC / 4; i += 256) orow4[i] = z;

    const float* lr = g_logits + (long)r * LE;
    float lam = g_lam[r];

    float vq[2], vc[2];
#pragma unroll
    for (int i = 0; i < 2; i++) {
        int e = t + i * 256;
        float l = lr[e];
        vq[i] = l + bq[b * LE + e];
        vc[i] = l + bc[b * LE + e];
    }

    __shared__ float red[256];
    red[t] = fmaxf(vq[0], vq[1]); __syncthreads();
    for (int o = 128; o > 0; o >>= 1) {
        if (t < o) red[t] = fmaxf(red[t], red[t + o]);
        __syncthreads();
    }
    float mq = red[0]; __syncthreads();
    red[t] = fmaxf(vc[0], vc[1]); __syncthreads();
    for (int o = 128; o > 0; o >>= 1) {
        if (t < o) red[t] = fmaxf(red[t], red[t + o]);
        __syncthreads();
    }
    float mc = red[0]; __syncthreads();

    float eq[2], ec[2], sq = 0.f, sc = 0.f;
#pragma unroll
    for (int i = 0; i < 2; i++) {
        eq[i] = __expf(vq[i] - mq); sq += eq[i];
        ec[i] = __expf(vc[i] - mc); sc += ec[i];
    }
    red[t] = sq; __syncthreads();
    for (int o = 128; o > 0; o >>= 1) {
        if (t < o) red[t] += red[t + o];
        __syncthreads();
    }
    sq = red[0]; __syncthreads();
    red[t] = sc; __syncthreads();
    for (int o = 128; o > 0; o >>= 1) {
        if (t < o) red[t] += red[t + o];
        __syncthreads();
    }
    sc = red[0];
    __syncthreads();   // zeros + reductions complete before scatter

    float iq = lam / sq, ic = (1.f - lam) / sc;
#pragma unroll
    for (int i = 0; i < 2; i++) {
        int e = t + i * 256;
        atomicAdd(orow + idx[b * LE + e], eq[i] * iq + ec[i] * ic);
    }
}

// ---------------------------------------------------------------------------
extern "C" void kernel_launch(void* const* d_in, const int* in_sizes, int n_in,
                              void* d_out, int out_size)
{
    const int*   inputs = (const int*)  d_in[0];
    const float* D      = (const float*)d_in[1];
    const float* Cq     = (const float*)d_in[2];
    const float* Cc     = (const float*)d_in[3];
    const float* Mi     = (const float*)d_in[4];
    const float* E      = (const float*)d_in[5];
    const float* bq     = (const float*)d_in[6];
    const float* bc     = (const float*)d_in[7];
    const float* Wl     = (const float*)d_in[8];
    const float* bl     = (const float*)d_in[9];
    const float* We     = (const float*)d_in[10];
    const float* Wm     = (const float*)d_in[11];
    float* out = (float*)d_out;

    float *gG, *gT, *gL;
    cudaGetSymbolAddress((void**)&gG, g_G);
    cudaGetSymbolAddress((void**)&gT, g_T);
    cudaGetSymbolAddress((void**)&gL, g_logits);

    const float scale = 0.044194173824159216f;  // 512^-0.5

    k_lambda<<<BSZ * LM, 256>>>(D, Cq, Cc, Wl, bl);

    // G = Wm @ We^T * scale      (512x512, K=512)  NT
    k_gemm_tc<true><<<dim3(8, 8, 1), 128>>>(Wm, We, gG, HD, HD, HD,
                                            0, 0, 0, scale);
    // T = M_flat @ G             (1024x512, K=512) NN
    k_gemm_tc<false><<<dim3(8, 16, 1), 128>>>(Mi, gG, gT, HD, HD, HD,
                                              0, 0, 0, 1.f);
    // logits[b] = T[b] @ E[b]^T  (256x512, K=512, batched over BS) NT
    k_gemm_tc<true><<<dim3(8, 4, BSZ), 128>>>(gT, E, gL, HD, HD, LE,
                                              (long)LM * HD, (long)LE * HD,
                                              (long)LM * LE, 1.f);

    k_softmax_scatter<<<BSZ * LM, 256>>>(inputs, bq, bc, out);
}